// round 11
// baseline (speedup 1.0000x reference)
#include <cuda_runtime.h>
#include <cuda_fp16.h>
#include <stdint.h>

// Problem constants
#define BB 2
#define NN 16384
#define KK 32
#define FF 64
#define EE 16
#define NT (BB * NN)      // 32768 nodes
#define SK (FF * EE)      // 1024 = GEMM contraction length

// Scratch (static __device__ arrays — no runtime allocation)
__device__ __align__(16) __half g_B[FF * SK];           // B[n][k] = w2^T (fp16)
__device__ __align__(16) __half g_Gh[(size_t)NT * FF];  // 4 MB: nodes in fp16

static __device__ __forceinline__ uint32_t hfpack(float hi, float lo) {
    uint32_t r;
    asm("cvt.rn.f16x2.f32 %0, %1, %2;" : "=r"(r) : "f"(hi), "f"(lo));
    return r;
}
static __device__ __forceinline__ uint32_t smem_u32(const void* p) {
    uint32_t a;
    asm("{ .reg .u64 t; cvta.to.shared.u64 t, %1; cvt.u32.u64 %0, t; }" : "=r"(a) : "l"(p));
    return a;
}
static __device__ __forceinline__ void ldsm4(uint32_t* r, uint32_t addr) {
    asm volatile("ldmatrix.sync.aligned.m8n8.x4.shared.b16 {%0,%1,%2,%3}, [%4];"
                 : "=r"(r[0]), "=r"(r[1]), "=r"(r[2]), "=r"(r[3]) : "r"(addr));
}
static __device__ __forceinline__ void ldsm4t(uint32_t* r, uint32_t addr) {
    asm volatile("ldmatrix.sync.aligned.m8n8.x4.trans.shared.b16 {%0,%1,%2,%3}, [%4];"
                 : "=r"(r[0]), "=r"(r[1]), "=r"(r[2]), "=r"(r[3]) : "r"(addr));
}
static __device__ __forceinline__ void sts32(uint32_t addr, uint32_t v) {
    asm volatile("st.shared.u32 [%0], %1;" :: "r"(addr), "r"(v) : "memory");
}
static __device__ __forceinline__ void mma16816h(float* c, const uint32_t* a,
                                                 const uint32_t* b) {
    asm volatile(
        "mma.sync.aligned.m16n8k16.row.col.f32.f16.f16.f32 "
        "{%0,%1,%2,%3}, {%4,%5,%6,%7}, {%8,%9}, {%0,%1,%2,%3};"
        : "+f"(c[0]), "+f"(c[1]), "+f"(c[2]), "+f"(c[3])
        : "r"(a[0]), "r"(a[1]), "r"(a[2]), "r"(a[3]), "r"(b[0]), "r"(b[1]));
}

// ---- kernel 0: nodes -> fp16 (g_Gh) + W2 transpose -> g_B (fp16) ----
__global__ __launch_bounds__(256) void k_conv(
    const float* __restrict__ nodes, const float* __restrict__ w)
{
    int t = blockIdx.x * 256 + threadIdx.x;          // 0 .. 524287
    float4 v = reinterpret_cast<const float4*>(nodes)[t];
    reinterpret_cast<uint2*>(g_Gh)[t] =
        make_uint2(hfpack(v.y, v.x), hfpack(v.w, v.z));
    if (t < FF * SK) {                               // id = n*1024 + k
        int n = t >> 10;
        int k = t & 1023;
        int l = k >> 4;
        int e = k & 15;
        g_B[t] = __float2half(w[l * (FF * EE) + n * EE + e]);
    }
}

// ================= fused kernel =================
// Block: 256 thr (8 warps), 32 nodes.
// Phase A (proven stage1): warp-per-node, 4 nodes/warp sequential; gather fp16
//   G + convert E, 16 HMMA per node; C fragments packed fp16 into a shared
//   S[32 x 1024h] smem matrix (pitch 2048B, XOR(row&7) 16B-unit swizzle).
// Phase C (proven stage2 core): out[32 x 64] = S @ W2, B streamed from L2 in
//   8 double-buffered chunks of 128 k. S never touches gmem.
#define GP 144                    // G row pitch bytes
#define EP 48                     // E row pitch bytes
#define GBYTES (32 * GP)          // 4608
#define EBYTES (32 * EP)          // 1536
#define NODE_SM (GBYTES + EBYTES)           // 6144
#define NPB 32                              // nodes per block
#define NPW 4                               // nodes per warp
#define S_BASE (8 * NODE_SM)                // 49152
#define SPITCH 2048                         // S row pitch bytes
#define SMEM_F (S_BASE + NPB * SPITCH)      // 114688
// phase-C B staging (aliases gather region after syncthreads)
#define KCH 128                             // k per chunk
#define BP 272                              // staged B row pitch (256 + 16)
#define BUFSZ (FF * BP)                     // 17408
#define BUF1 BUFSZ

__global__ __launch_bounds__(256, 2) void k_fused(
    const int*   __restrict__ nlist,
    const float* __restrict__ edges,
    float* __restrict__ out)
{
    extern __shared__ __align__(16) char sm[];
    const int t    = threadIdx.x;
    const int w    = t >> 5;
    const int lane = t & 31;
    const int g0   = blockIdx.x * NPB;
    const int b    = g0 >> 14;
    const uint32_t smb = smem_u32(sm);

    char* base = sm + w * NODE_SM;
    const uint32_t sb = smb + w * NODE_SM;
    const __half* nbase = g_Gh + (size_t)b * (NN * FF);

    // phase-A fragment addresses (proven stage1 mappings)
    const uint32_t aA = sb + ((lane & 7) + 8 * (lane >> 4)) * GP
                           + ((lane >> 3) & 1) * 16;
    const uint32_t aB = sb + GBYTES
                           + ((lane & 7) + 8 * ((lane >> 3) & 1)) * EP
                           + (lane >> 4) * 16;
    const int l4   = lane & 7;
    const int rsub = lane >> 3;
    const int r    = lane >> 2;
    const int q4   = 4 * (lane & 3);

    // ================= phase A =================
    for (int it = 0; it < NPW; it++) {
        const int nr = w * NPW + it;            // node row within block
        const int g  = g0 + nr;
        const int my_idx = nlist[(size_t)g * KK + lane];

        // gather G (fp16, 128B rows): 8 LDG.128 batched for MLP
        {
            uint4 gv[8];
#pragma unroll
            for (int p = 0; p < 8; p++) {
                int j = p * 4 + rsub;
                int jdx = __shfl_sync(0xffffffffu, my_idx, j);
                gv[p] = *reinterpret_cast<const uint4*>(
                    nbase + (size_t)jdx * FF + l4 * 8);
            }
#pragma unroll
            for (int p = 0; p < 8; p++)
                *reinterpret_cast<uint4*>(base + (p * 4 + rsub) * GP + l4 * 16) = gv[p];
        }
        // E: 32 x 16 fp32 -> fp16 with exact 1/32
        {
            const float4* ef = reinterpret_cast<const float4*>(edges) + (size_t)g * 128;
#pragma unroll
            for (int qq = 0; qq < 4; qq++) {
                int u = qq * 32 + lane;
                float4 v = ef[u];
                int j = u >> 2, n4 = u & 3;
                *reinterpret_cast<uint2*>(base + GBYTES + j * EP + n4 * 8) =
                    make_uint2(hfpack(v.y * 0.03125f, v.x * 0.03125f),
                               hfpack(v.w * 0.03125f, v.z * 0.03125f));
            }
        }
        __syncwarp();

        float C[4][2][4];
#pragma unroll
        for (int mt = 0; mt < 4; mt++)
#pragma unroll
            for (int nt = 0; nt < 2; nt++)
#pragma unroll
                for (int i = 0; i < 4; i++) C[mt][nt][i] = 0.0f;

#pragma unroll
        for (int ks = 0; ks < 2; ks++) {
            uint32_t bh[4];
            ldsm4t(bh, aB + ks * 16 * EP);
#pragma unroll
            for (int mt = 0; mt < 4; mt++) {
                uint32_t ah[4];
                ldsm4t(ah, aA + ks * 16 * GP + mt * 32);
                mma16816h(C[mt][0], ah, bh);
                mma16816h(C[mt][1], ah, bh + 2);
            }
        }
        __syncwarp();   // ldsm consumed before next iteration overwrites

        // pack fp16 -> shared S row nr with XOR(row&7) 16B-unit swizzle
        const int x = nr & 7;
        const uint32_t rowb = smb + S_BASE + nr * SPITCH;
#pragma unroll
        for (int mt = 0; mt < 4; mt++) {
#pragma unroll
            for (int nt = 0; nt < 2; nt++) {
                int u0 = 2 * (mt * 16 + r) + nt;        // 16B unit of (c0,c1)
                sts32(rowb + ((u0 ^ x) << 4) + q4,
                      hfpack(C[mt][nt][1], C[mt][nt][0]));
                sts32(rowb + (((u0 + 16) ^ x) << 4) + q4,   // l+8 rows
                      hfpack(C[mt][nt][3], C[mt][nt][2]));
            }
        }
    }
    __syncthreads();

    // ================= phase C: out[32 x 64] = S @ W2 =================
    const int mt = w & 1;                       // m-tile (16 nodes)
    const int ng = w >> 1;                      // n-group (2 n-tiles = 16 cols)
    const int arow = mt * 16 + (lane & 7) + 8 * ((lane >> 3) & 1);
    const int ua   = lane >> 4;
    const int ax   = arow & 7;
    const uint32_t aArow = smb + S_BASE + arow * SPITCH;
    const uint32_t bfoff = (16 * ng + 8 * (lane >> 4) + (lane & 7)) * BP
                         + ((lane >> 3) & 1) * 16;

    float acc[2][4];
#pragma unroll
    for (int nt = 0; nt < 2; nt++)
#pragma unroll
        for (int i = 0; i < 4; i++) acc[nt][i] = 0.0f;

    for (int c = 0; c < SK / KCH; c++) {        // 8 chunks
        // prefetch B chunk (64 n x 128 k fp16 = 16 KB) from L2
        uint4 rb[4];
#pragma unroll
        for (int qq = 0; qq < 4; qq++) {
            int u = t + qq * 256;               // 0..1023
            int n = u >> 4, j = u & 15;
            rb[qq] = *reinterpret_cast<const uint4*>(g_B + (size_t)n * SK + c * KCH + j * 8);
        }
        const uint32_t buf = (c & 1) ? BUF1 : 0;
#pragma unroll
        for (int qq = 0; qq < 4; qq++) {
            int u = t + qq * 256;
            int n = u >> 4, j = u & 15;
            *reinterpret_cast<uint4*>(sm + buf + n * BP + j * 16) = rb[qq];
        }
        __syncthreads();                        // double-buffered: 1 sync/chunk

#pragma unroll
        for (int ks = 0; ks < KCH / 16; ks++) {
            const int ku = c * 16 + ks * 2 + ua;
            uint32_t a[4];
            ldsm4(a, aArow + ((uint32_t)(ku ^ ax) << 4));
            uint32_t bf[4];
            ldsm4(bf, smb + buf + bfoff + ks * 32);
            mma16816h(acc[0], a, bf);
            mma16816h(acc[1], a, bf + 2);
        }
    }

    // epilogue
    const int cb = 2 * (lane & 3);
    const int row0 = g0 + mt * 16 + (lane >> 2);
#pragma unroll
    for (int nt = 0; nt < 2; nt++) {
        int col = (2 * ng + nt) * 8 + cb;
        *reinterpret_cast<float2*>(out + (size_t)row0 * FF + col) =
            make_float2(acc[nt][0], acc[nt][1]);
        *reinterpret_cast<float2*>(out + (size_t)(row0 + 8) * FF + col) =
            make_float2(acc[nt][2], acc[nt][3]);
    }
}

extern "C" void kernel_launch(void* const* d_in, const int* in_sizes, int n_in,
                              void* d_out, int out_size) {
    const float* nodes = (const float*)d_in[0];
    const int*   nlist = (const int*)d_in[1];
    const float* edges = (const float*)d_in[2];
    const float* w     = (const float*)d_in[3];
    float* out = (float*)d_out;
    (void)in_sizes; (void)n_in; (void)out_size;

    cudaFuncSetAttribute(k_fused,
                         cudaFuncAttributeMaxDynamicSharedMemorySize, SMEM_F);

    k_conv<<<NT * FF / 4 / 256, 256>>>(nodes, w);
    k_fused<<<NT / NPB, 256, SMEM_F>>>(nlist, edges, out);
}